// round 1
// baseline (speedup 1.0000x reference)
#include <cuda_runtime.h>

#define NN 1024
#define EPSF 1e-16f

// Scratch (static __device__ — no allocation)
__device__ float g_Xt[NN * NN];      // X transpose, 4MB
__device__ float g_rowlsum[NN];      // sum_j log(1-X[i,j]+EPS)
__device__ float g_elbrow[NN];       // per-row elb term (incl. exp factor)
__device__ float g_part[NN];         // per-block elb partial from main kernel

// ---------------------------------------------------------------------------
// Kernel 0: tiled transpose X -> g_Xt
// ---------------------------------------------------------------------------
__global__ void k_transpose(const float* __restrict__ X) {
    __shared__ float tile[32][33];
    int bx = blockIdx.x * 32, by = blockIdx.y * 32;
    int tx = threadIdx.x, ty = threadIdx.y;
#pragma unroll
    for (int r = 0; r < 32; r += 8)
        tile[ty + r][tx] = X[(by + ty + r) * NN + bx + tx];
    __syncthreads();
#pragma unroll
    for (int r = 0; r < 32; r += 8)
        g_Xt[(bx + ty + r) * NN + by + tx] = tile[tx][ty + r];
}

// ---------------------------------------------------------------------------
// Kernel 1: per-row prep — row_lsum, sum(XX_), and the iT product term
// ---------------------------------------------------------------------------
__global__ void __launch_bounds__(256) k_rowprep(
    const float* __restrict__ X,
    const int* __restrict__ iT,     // (N, 21, 2)
    const float* __restrict__ B0,
    const float* __restrict__ B1,
    const float* __restrict__ B2)
{
    int i = blockIdx.x, tid = threadIdx.x;
    __shared__ float xs[NN];
    __shared__ float red[256];

    float lsum_l = 0.f, xxsum_l = 0.f;
    for (int j = tid; j < NN; j += 256) {
        float x = X[i * NN + j];
        xs[j] = x;
        float x_ = 1.f - x + EPSF;
        lsum_l += logf(x_);
        xxsum_l += x / x_;
    }
    __syncthreads();

    red[tid] = lsum_l;
    __syncthreads();
    for (int s = 128; s > 0; s >>= 1) { if (tid < s) red[tid] += red[tid + s]; __syncthreads(); }
    float lsum = red[0];
    __syncthreads();

    red[tid] = xxsum_l;
    __syncthreads();
    for (int s = 128; s > 0; s >>= 1) { if (tid < s) red[tid] += red[tid + s]; __syncthreads(); }
    float xxsum = red[0];
    __syncthreads();

    float spl = 0.f;
    if (tid < 21) {
        int ka = iT[(i * 21 + tid) * 2 + 0];
        int kb = iT[(i * 21 + tid) * 2 + 1];
        float xa = xs[ka], xb = xs[kb];
        spl = (xa / (1.f - xa + EPSF)) * (xb / (1.f - xb + EPSF));
    }
    red[tid] = spl;
    __syncthreads();
    for (int s = 128; s > 0; s >>= 1) { if (tid < s) red[tid] += red[tid + s]; __syncthreads(); }

    if (tid == 0) {
        float sp = red[0];
        g_rowlsum[i] = lsum;
        g_elbrow[i] = (B0[0] + xxsum * B1[0] + sp * B2[0]) * expf(lsum);
    }
}

// ---------------------------------------------------------------------------
// Kernel 2: main — gamma/sigmoid output + elementwise elb partials
// ---------------------------------------------------------------------------
__global__ void __launch_bounds__(256) k_main(
    const float* __restrict__ X,
    const float* __restrict__ C,
    const float* __restrict__ D,
    const float* __restrict__ S,
    const float* __restrict__ Mk,
    const float* __restrict__ Tt,
    const float* __restrict__ B0, const float* __restrict__ B1, const float* __restrict__ B2,
    const float* __restrict__ LAM, const float* __restrict__ ETA,
    const float* __restrict__ NU, const float* __restrict__ MU,
    const float* __restrict__ KAP,
    const int* __restrict__ Iij,     // (N,N,6)
    const int* __restrict__ IijF,    // (N,N,6)
    const int* __restrict__ IijT,    // (N,N,6,5)
    float* __restrict__ out)
{
    int i = blockIdx.x, tid = threadIdx.x;
    __shared__ float xs[NN];
    __shared__ float xxs[NN];
    __shared__ float red[256];

    for (int j = tid; j < NN; j += 256) {
        float x = X[i * NN + j];
        xs[j] = x;
        xxs[j] = x / (1.f - x + EPSF);
    }
    __syncthreads();

    float t = Tt[0];
    float b0 = B0[0], b1 = B1[0], b2 = B2[0];
    float lam = LAM[0], eta = ETA[0], nu = NU[0], mu = MU[0];
    float k0 = KAP[0], k1 = KAP[1], k2 = KAP[2], k3 = KAP[3], k4 = KAP[4], k5 = KAP[5];
    float Ksum = ((k0 + k1) + (k2 + k3)) + (k4 + k5);
    float rls = g_rowlsum[i];
    float invt = 1.f / t;

    float acc = 0.f;
    for (int j = tid; j < NN; j += 256) {
        size_t e = (size_t)i * NN + j;
        float x = xs[j];
        float xt = g_Xt[e];
        float x_ = 1.f - x + EPSF;
        float lx_ = logf(x_);
        float tmp0 = expf(rls - lx_);
        float pair = lam + eta * D[e] + nu * C[e] + mu * S[e];
        float m = Mk[e];

        // 6 indices for ij (gX + XX gathers)
        const int2* pij = (const int2*)(Iij + e * 6);
        int2 a0 = pij[0], a1 = pij[1], a2 = pij[2];
        float locUp0 = xxs[a0.x] + xxs[a0.y] + xxs[a1.x] + xxs[a1.y] + xxs[a2.x] + xxs[a2.y];
        float skap = k0 * xs[a0.x] + k1 * xs[a0.y] + k2 * xs[a1.x]
                   + k3 * xs[a1.y] + k4 * xs[a2.x] + k5 * xs[a2.y];

        // 6 F indices + 30 T indices
        const int2* pF = (const int2*)(IijF + e * 6);
        int2 f0 = pF[0], f1 = pF[1], f2 = pF[2];
        const int2* pT = (const int2*)(IijT + e * 30);
        int2 t0 = pT[0], t1 = pT[1], t2 = pT[2], t3 = pT[3], t4 = pT[4];
        int2 t5 = pT[5], t6 = pT[6], t7 = pT[7], t8 = pT[8], t9 = pT[9];
        int2 ta = pT[10], tb = pT[11], tc = pT[12], td = pT[13], te = pT[14];

        float s0 = xxs[t0.x] + xxs[t0.y] + xxs[t1.x] + xxs[t1.y] + xxs[t2.x];
        float s1 = xxs[t2.y] + xxs[t3.x] + xxs[t3.y] + xxs[t4.x] + xxs[t4.y];
        float s2 = xxs[t5.x] + xxs[t5.y] + xxs[t6.x] + xxs[t6.y] + xxs[t7.x];
        float s3 = xxs[t7.y] + xxs[t8.x] + xxs[t8.y] + xxs[t9.x] + xxs[t9.y];
        float s4 = xxs[ta.x] + xxs[ta.y] + xxs[tb.x] + xxs[tb.y] + xxs[tc.x];
        float s5 = xxs[tc.y] + xxs[td.x] + xxs[td.y] + xxs[te.x] + xxs[te.y];

        float locUp1 = xxs[f0.x] * s0 + xxs[f0.y] * s1 + xxs[f1.x] * s2
                     + xxs[f1.y] * s3 + xxs[f2.x] * s4 + xxs[f2.y] * s5;

        float gamma = (b1 - b0 + (b2 - b1) * locUp0 - b2 * locUp1) * tmp0
                    + (4.f * xt - 2.f) * pair
                    + 100.f * (m - 1.f)
                    + (4.f * skap - 2.f * Ksum);

        out[1 + e] = 1.f / (1.f + expf(-gamma * invt));

        // elb elementwise contributions:
        //  pair*(1 + 4 x xt - 2(x+xt))*m
        //  + (1-2x)*(K - 2*skap)*m        [ = sum_d term3 ]
        //  - t*(x*log(x+eps) + x_*lx_)*m
        float ent = x * logf(x + EPSF) + x_ * lx_;
        acc += m * (pair * (1.f + 4.f * x * xt - 2.f * (x + xt))
                    + (1.f - 2.f * x) * (Ksum - 2.f * skap)
                    - t * ent);
    }

    red[tid] = acc;
    __syncthreads();
    for (int s = 128; s > 0; s >>= 1) { if (tid < s) red[tid] += red[tid + s]; __syncthreads(); }
    if (tid == 0) g_part[i] = red[0];
}

// ---------------------------------------------------------------------------
// Kernel 3: final deterministic reduction (double)
// ---------------------------------------------------------------------------
__global__ void k_final(float* __restrict__ out) {
    __shared__ double red[1024];
    int tid = threadIdx.x;
    red[tid] = (double)g_part[tid] + (double)g_elbrow[tid];
    __syncthreads();
    for (int s = 512; s > 0; s >>= 1) { if (tid < s) red[tid] += red[tid + s]; __syncthreads(); }
    if (tid == 0) out[0] = (float)red[0];
}

// ---------------------------------------------------------------------------
extern "C" void kernel_launch(void* const* d_in, const int* in_sizes, int n_in,
                              void* d_out, int out_size) {
    const float* X    = (const float*)d_in[0];
    const float* T    = (const float*)d_in[1];
    const float* C    = (const float*)d_in[2];
    const float* D    = (const float*)d_in[3];
    const float* S    = (const float*)d_in[4];
    const float* Mk   = (const float*)d_in[5];
    const float* b0   = (const float*)d_in[6];
    const float* b1   = (const float*)d_in[7];
    const float* b2   = (const float*)d_in[8];
    const float* lam  = (const float*)d_in[9];
    const float* eta  = (const float*)d_in[10];
    const float* nu   = (const float*)d_in[11];
    const float* mu   = (const float*)d_in[12];
    const float* kap  = (const float*)d_in[13];
    const int*   iij  = (const int*)d_in[14];
    const int*   iijF = (const int*)d_in[15];
    const int*   iijT = (const int*)d_in[16];
    const int*   iiT  = (const int*)d_in[17];
    float* out = (float*)d_out;

    k_transpose<<<dim3(32, 32), dim3(32, 8)>>>(X);
    k_rowprep<<<NN, 256>>>(X, iiT, b0, b1, b2);
    k_main<<<NN, 256>>>(X, C, D, S, Mk, T, b0, b1, b2, lam, eta, nu, mu, kap,
                        iij, iijF, iijT, out);
    k_final<<<1, 1024>>>(out);
}

// round 2
// speedup vs baseline: 1.1227x; 1.1227x over previous
#include <cuda_runtime.h>

#define NN 1024
#define EPSF 1e-16f

// Static scratch (no allocation)
__device__ float g_Xt[NN * NN];      // X transpose
__device__ float g_part[NN];         // per-row elb partial
__device__ unsigned int g_ctr;       // block-done counter, wraps to 0

// ---------------------------------------------------------------------------
// Kernel 0: tiled transpose X -> g_Xt
// ---------------------------------------------------------------------------
__global__ void k_transpose(const float* __restrict__ X) {
    __shared__ float tile[32][33];
    int bx = blockIdx.x * 32, by = blockIdx.y * 32;
    int tx = threadIdx.x, ty = threadIdx.y;
#pragma unroll
    for (int r = 0; r < 32; r += 8)
        tile[ty + r][tx] = X[(by + ty + r) * NN + bx + tx];
    __syncthreads();
#pragma unroll
    for (int r = 0; r < 32; r += 8)
        g_Xt[(bx + ty + r) * NN + by + tx] = tile[tx][ty + r];
}

__device__ __forceinline__ float wred(float v) {
#pragma unroll
    for (int o = 16; o; o >>= 1) v += __shfl_down_sync(0xffffffffu, v, o);
    return v;
}
__device__ __forceinline__ double wredd(double v) {
#pragma unroll
    for (int o = 16; o; o >>= 1) v += __shfl_down_sync(0xffffffffu, v, o);
    return v;
}

// ---------------------------------------------------------------------------
// Kernel 1: fused main — rowprep + gamma/sigmoid + elb partial + final reduce
// ---------------------------------------------------------------------------
__global__ void __launch_bounds__(256) k_main(
    const float* __restrict__ X,
    const float* __restrict__ C,
    const float* __restrict__ D,
    const float* __restrict__ S,
    const float* __restrict__ Mk,
    const float* __restrict__ Tt,
    const float* __restrict__ B0, const float* __restrict__ B1, const float* __restrict__ B2,
    const float* __restrict__ LAM, const float* __restrict__ ETA,
    const float* __restrict__ NU, const float* __restrict__ MU,
    const float* __restrict__ KAP,
    const int* __restrict__ Iij,     // (N,N,6)
    const int* __restrict__ IijF,    // (N,N,6)
    const int* __restrict__ IijT,    // (N,N,6,5)
    const int* __restrict__ IiT,     // (N,21,2)
    float* __restrict__ out)
{
    int i = blockIdx.x, tid = threadIdx.x;
    __shared__ float  xxs[NN];       // x/(1-x+eps)
    __shared__ float2 xg[NN];        // (x, xx)
    __shared__ float  redA[8], redB[8], redC[8];
    __shared__ double redD[8];
    __shared__ float  s_spl;
    __shared__ bool   s_last;

    // ---- prologue: load row i, build smem, local sums ----
    float lsum = 0.f, xxsum = 0.f;
    {
        float4 xq = ((const float4*)(X + (size_t)i * NN))[tid];
        float xs4[4] = {xq.x, xq.y, xq.z, xq.w};
#pragma unroll
        for (int k = 0; k < 4; k++) {
            int j = tid * 4 + k;
            float x  = xs4[k];
            float x_ = 1.f - x + EPSF;
            float xx = __fdividef(x, x_);
            xxs[j] = xx;
            xg[j]  = make_float2(x, xx);
            lsum  += __logf(x_);
            xxsum += xx;
        }
    }
    __syncthreads();

    float wa = wred(lsum), wb = wred(xxsum);
    if ((tid & 31) == 0) { redA[tid >> 5] = wa; redB[tid >> 5] = wb; }
    __syncthreads();
    float rls = 0.f, xxsumT = 0.f;
#pragma unroll
    for (int w = 0; w < 8; w++) { rls += redA[w]; xxsumT += redB[w]; }

    // ---- iT: sum of 21 products xxs[a]*xxs[b] (warp 0 only) ----
    if (tid < 32) {
        float spl = 0.f;
        if (tid < 21) {
            int ka = IiT[((size_t)i * 21 + tid) * 2 + 0];
            int kb = IiT[((size_t)i * 21 + tid) * 2 + 1];
            spl = xxs[ka] * xxs[kb];
        }
        spl = wred(spl);
        if (tid == 0) s_spl = spl;
    }

    // ---- scalars ----
    float t  = Tt[0];
    float b0v = B0[0], b1v = B1[0], b2v = B2[0];
    float lam = LAM[0], eta = ETA[0], nu = NU[0], mu = MU[0];
    float k0 = KAP[0], k1 = KAP[1], k2 = KAP[2], k3 = KAP[3], k4 = KAP[4], k5 = KAP[5];
    float Ksum = ((k0 + k1) + (k2 + k3)) + (k4 + k5);
    float twoK = 2.f * Ksum;
    float b1b0 = b1v - b0v, b2b1 = b2v - b1v;
    float invt = __fdividef(1.f, t);

    const int4*   pIJ = (const int4*)(Iij  + (size_t)i * NN * 6);
    const int4*   pF  = (const int4*)(IijF + (size_t)i * NN * 6);
    const int4*   pT  = (const int4*)(IijT + (size_t)i * NN * 30);
    const float2* pC  = (const float2*)(C    + (size_t)i * NN);
    const float2* pD  = (const float2*)(D    + (size_t)i * NN);
    const float2* pS  = (const float2*)(S    + (size_t)i * NN);
    const float2* pM  = (const float2*)(Mk   + (size_t)i * NN);
    const float2* pXt = (const float2*)(g_Xt + (size_t)i * NN);
    float* outg = out + 1 + (size_t)i * NN;

    float acc = 0.f;
#pragma unroll
    for (int itc = 0; itc < 2; ++itc) {
        int p  = tid + itc * 256;   // pair index 0..511
        int j0 = 2 * p;

        int4 q0 = pIJ[p*3+0], q1 = pIJ[p*3+1], q2 = pIJ[p*3+2];
        int4 r0 = pF [p*3+0], r1 = pF [p*3+1], r2 = pF [p*3+2];
        int4 u0 = pT[p*15+0], u1 = pT[p*15+1], u2 = pT[p*15+2], u3 = pT[p*15+3];
        int4 u4 = pT[p*15+4], u5 = pT[p*15+5], u6 = pT[p*15+6], u7 = pT[p*15+7];
        float2 Cv = pC[p], Dv = pD[p], Sv = pS[p], Mv = pM[p], Xtv = pXt[p];

        // ===== element 0 (column j0) =====
        {
            float2 g0 = xg[q0.x], g1 = xg[q0.y], g2 = xg[q0.z],
                   g3 = xg[q0.w], g4 = xg[q1.x], g5 = xg[q1.y];
            float locUp0 = ((g0.y + g1.y) + (g2.y + g3.y)) + (g4.y + g5.y);
            float skap = k0*g0.x + k1*g1.x + k2*g2.x + k3*g3.x + k4*g4.x + k5*g5.x;

            float f0 = xxs[r0.x], f1 = xxs[r0.y], f2 = xxs[r0.z],
                  f3 = xxs[r0.w], f4 = xxs[r1.x], f5 = xxs[r1.y];
            float s0 = xxs[u0.x]+xxs[u0.y]+xxs[u0.z]+xxs[u0.w]+xxs[u1.x];
            float s1 = xxs[u1.y]+xxs[u1.z]+xxs[u1.w]+xxs[u2.x]+xxs[u2.y];
            float s2 = xxs[u2.z]+xxs[u2.w]+xxs[u3.x]+xxs[u3.y]+xxs[u3.z];
            float s3 = xxs[u3.w]+xxs[u4.x]+xxs[u4.y]+xxs[u4.z]+xxs[u4.w];
            float s4 = xxs[u5.x]+xxs[u5.y]+xxs[u5.z]+xxs[u5.w]+xxs[u6.x];
            float s5 = xxs[u6.y]+xxs[u6.z]+xxs[u6.w]+xxs[u7.x]+xxs[u7.y];
            float locUp1 = f0*s0 + f1*s1 + f2*s2 + f3*s3 + f4*s4 + f5*s5;

            float xv = xg[j0].x;
            float xt = Xtv.x;
            float x_ = 1.f - xv + EPSF;
            float lx_ = __logf(x_);
            float tmp0 = __expf(rls - lx_);
            float pr = lam + eta*Dv.x + nu*Cv.x + mu*Sv.x;
            float m  = Mv.x;
            float gm = (b1b0 + b2b1*locUp0 - b2v*locUp1)*tmp0
                     + (4.f*xt - 2.f)*pr + 100.f*(m - 1.f) + (4.f*skap - twoK);
            outg[j0] = __fdividef(1.f, 1.f + __expf(-gm*invt));
            float ent = xv*__logf(xv + EPSF) + x_*lx_;
            acc += m*( pr*(1.f + 4.f*xv*xt - 2.f*(xv + xt))
                     + (1.f - 2.f*xv)*(Ksum - 2.f*skap) - t*ent );
        }

        // ===== element 1 (column j0+1) =====
        {
            int4 u8  = pT[p*15+8],  u9  = pT[p*15+9],  u10 = pT[p*15+10];
            int4 u11 = pT[p*15+11], u12 = pT[p*15+12], u13 = pT[p*15+13], u14 = pT[p*15+14];

            float2 g0 = xg[q1.z], g1 = xg[q1.w], g2 = xg[q2.x],
                   g3 = xg[q2.y], g4 = xg[q2.z], g5 = xg[q2.w];
            float locUp0 = ((g0.y + g1.y) + (g2.y + g3.y)) + (g4.y + g5.y);
            float skap = k0*g0.x + k1*g1.x + k2*g2.x + k3*g3.x + k4*g4.x + k5*g5.x;

            float f0 = xxs[r1.z], f1 = xxs[r1.w], f2 = xxs[r2.x],
                  f3 = xxs[r2.y], f4 = xxs[r2.z], f5 = xxs[r2.w];
            float s0 = xxs[u7.z]+xxs[u7.w]+xxs[u8.x]+xxs[u8.y]+xxs[u8.z];
            float s1 = xxs[u8.w]+xxs[u9.x]+xxs[u9.y]+xxs[u9.z]+xxs[u9.w];
            float s2 = xxs[u10.x]+xxs[u10.y]+xxs[u10.z]+xxs[u10.w]+xxs[u11.x];
            float s3 = xxs[u11.y]+xxs[u11.z]+xxs[u11.w]+xxs[u12.x]+xxs[u12.y];
            float s4 = xxs[u12.z]+xxs[u12.w]+xxs[u13.x]+xxs[u13.y]+xxs[u13.z];
            float s5 = xxs[u13.w]+xxs[u14.x]+xxs[u14.y]+xxs[u14.z]+xxs[u14.w];
            float locUp1 = f0*s0 + f1*s1 + f2*s2 + f3*s3 + f4*s4 + f5*s5;

            float xv = xg[j0 + 1].x;
            float xt = Xtv.y;
            float x_ = 1.f - xv + EPSF;
            float lx_ = __logf(x_);
            float tmp0 = __expf(rls - lx_);
            float pr = lam + eta*Dv.y + nu*Cv.y + mu*Sv.y;
            float m  = Mv.y;
            float gm = (b1b0 + b2b1*locUp0 - b2v*locUp1)*tmp0
                     + (4.f*xt - 2.f)*pr + 100.f*(m - 1.f) + (4.f*skap - twoK);
            outg[j0 + 1] = __fdividef(1.f, 1.f + __expf(-gm*invt));
            float ent = xv*__logf(xv + EPSF) + x_*lx_;
            acc += m*( pr*(1.f + 4.f*xv*xt - 2.f*(xv + xt))
                     + (1.f - 2.f*xv)*(Ksum - 2.f*skap) - t*ent );
        }
    }

    // ---- block reduction of acc; emit per-row partial ----
    __syncthreads();                 // protects s_spl and smem reuse ordering
    float ar = wred(acc);
    if ((tid & 31) == 0) redC[tid >> 5] = ar;
    __syncthreads();
    if (tid == 0) {
        float tot = 0.f;
#pragma unroll
        for (int w = 0; w < 8; w++) tot += redC[w];
        float elbrow = (b0v + xxsumT*b1v + s_spl*b2v) * __expf(rls);
        g_part[i] = tot + elbrow;
        __threadfence();
        unsigned int old = atomicInc(&g_ctr, NN - 1);   // wraps to 0 after NN incs
        s_last = (old == NN - 1);
    }
    __syncthreads();

    // ---- last block: deterministic final sum in double ----
    if (s_last) {
        double dv = 0.0;
#pragma unroll
        for (int w = 0; w < 4; w++) dv += (double)g_part[tid + w * 256];
        double dr = wredd(dv);
        if ((tid & 31) == 0) redD[tid >> 5] = dr;
        __syncthreads();
        if (tid == 0) {
            double tt = 0.0;
#pragma unroll
            for (int w = 0; w < 8; w++) tt += redD[w];
            out[0] = (float)tt;
        }
    }
}

// ---------------------------------------------------------------------------
extern "C" void kernel_launch(void* const* d_in, const int* in_sizes, int n_in,
                              void* d_out, int out_size) {
    const float* X    = (const float*)d_in[0];
    const float* T    = (const float*)d_in[1];
    const float* C    = (const float*)d_in[2];
    const float* D    = (const float*)d_in[3];
    const float* S    = (const float*)d_in[4];
    const float* Mk   = (const float*)d_in[5];
    const float* b0   = (const float*)d_in[6];
    const float* b1   = (const float*)d_in[7];
    const float* b2   = (const float*)d_in[8];
    const float* lam  = (const float*)d_in[9];
    const float* eta  = (const float*)d_in[10];
    const float* nu   = (const float*)d_in[11];
    const float* mu   = (const float*)d_in[12];
    const float* kap  = (const float*)d_in[13];
    const int*   iij  = (const int*)d_in[14];
    const int*   iijF = (const int*)d_in[15];
    const int*   iijT = (const int*)d_in[16];
    const int*   iiT  = (const int*)d_in[17];
    float* out = (float*)d_out;

    k_transpose<<<dim3(32, 32), dim3(32, 8)>>>(X);
    k_main<<<NN, 256>>>(X, C, D, S, Mk, T, b0, b1, b2, lam, eta, nu, mu, kap,
                        iij, iijF, iijT, iiT, out);
}

// round 3
// speedup vs baseline: 1.3662x; 1.2168x over previous
#include <cuda_runtime.h>

#define NN 1024
#define EPSF 1e-16f

// Static scratch (no allocation)
__device__ float g_Xt[NN * NN];      // X transpose
__device__ float g_part[NN];         // per-row elb partial
__device__ unsigned int g_ctr;       // block-done counter, wraps to 0

// ---------------------------------------------------------------------------
// Kernel 0: tiled transpose X -> g_Xt
// ---------------------------------------------------------------------------
__global__ void k_transpose(const float* __restrict__ X) {
    __shared__ float tile[32][33];
    int bx = blockIdx.x * 32, by = blockIdx.y * 32;
    int tx = threadIdx.x, ty = threadIdx.y;
#pragma unroll
    for (int r = 0; r < 32; r += 8)
        tile[ty + r][tx] = X[(by + ty + r) * NN + bx + tx];
    __syncthreads();
#pragma unroll
    for (int r = 0; r < 32; r += 8)
        g_Xt[(bx + ty + r) * NN + by + tx] = tile[tx][ty + r];
}

__device__ __forceinline__ float wred(float v) {
#pragma unroll
    for (int o = 16; o; o >>= 1) v += __shfl_down_sync(0xffffffffu, v, o);
    return v;
}
__device__ __forceinline__ double wredd(double v) {
#pragma unroll
    for (int o = 16; o; o >>= 1) v += __shfl_down_sync(0xffffffffu, v, o);
    return v;
}

// ---------------------------------------------------------------------------
// Kernel 1: fused main — rowprep + gamma/sigmoid + elb partial + final reduce
// 512 threads, one column-pair per thread.
// ---------------------------------------------------------------------------
__global__ void __launch_bounds__(512, 2) k_main(
    const float* __restrict__ X,
    const float* __restrict__ C,
    const float* __restrict__ D,
    const float* __restrict__ S,
    const float* __restrict__ Mk,
    const float* __restrict__ Tt,
    const float* __restrict__ B0, const float* __restrict__ B1, const float* __restrict__ B2,
    const float* __restrict__ LAM, const float* __restrict__ ETA,
    const float* __restrict__ NU, const float* __restrict__ MU,
    const float* __restrict__ KAP,
    const int* __restrict__ Iij,     // (N,N,6)
    const int* __restrict__ IijF,    // (N,N,6)
    const int* __restrict__ IijT,    // (N,N,6,5)
    const int* __restrict__ IiT,     // (N,21,2)
    float* __restrict__ out)
{
    int i = blockIdx.x, tid = threadIdx.x;
    __shared__ float  xxs[NN];       // x/(1-x+eps)
    __shared__ float2 xg[NN];        // (x, xx)
    __shared__ float  redA[16], redB[16], redC[16];
    __shared__ double redD[16];
    __shared__ float  s_spl;
    __shared__ bool   s_last;

    // ---- prologue: load row i, build smem, local sums ----
    float lsum = 0.f, xxsum = 0.f;
    {
        float2 xq = ((const float2*)(X + (size_t)i * NN))[tid];
        float xs2[2] = {xq.x, xq.y};
#pragma unroll
        for (int k = 0; k < 2; k++) {
            int j = tid * 2 + k;
            float x  = xs2[k];
            float x_ = 1.f - x + EPSF;
            float xx = __fdividef(x, x_);
            xxs[j] = xx;
            xg[j]  = make_float2(x, xx);
            lsum  += __logf(x_);
            xxsum += xx;
        }
    }
    __syncthreads();

    float wa = wred(lsum), wb = wred(xxsum);
    if ((tid & 31) == 0) { redA[tid >> 5] = wa; redB[tid >> 5] = wb; }
    __syncthreads();
    float rls = 0.f, xxsumT = 0.f;
#pragma unroll
    for (int w = 0; w < 16; w++) { rls += redA[w]; xxsumT += redB[w]; }

    // ---- iT: sum of 21 products xxs[a]*xxs[b] (warp 0 only) ----
    if (tid < 32) {
        float spl = 0.f;
        if (tid < 21) {
            int ka = IiT[((size_t)i * 21 + tid) * 2 + 0];
            int kb = IiT[((size_t)i * 21 + tid) * 2 + 1];
            spl = xxs[ka] * xxs[kb];
        }
        spl = wred(spl);
        if (tid == 0) s_spl = spl;
    }

    // ---- scalars ----
    float t  = Tt[0];
    float b0v = B0[0], b1v = B1[0], b2v = B2[0];
    float lam = LAM[0], eta = ETA[0], nu = NU[0], mu = MU[0];
    float k0 = KAP[0], k1 = KAP[1], k2 = KAP[2], k3 = KAP[3], k4 = KAP[4], k5 = KAP[5];
    float Ksum = ((k0 + k1) + (k2 + k3)) + (k4 + k5);
    float twoK = 2.f * Ksum;
    float b1b0 = b1v - b0v, b2b1 = b2v - b1v;
    float invt = __fdividef(1.f, t);

    const int4*   pIJ = (const int4*)(Iij  + (size_t)i * NN * 6);
    const int4*   pF  = (const int4*)(IijF + (size_t)i * NN * 6);
    const int4*   pT  = (const int4*)(IijT + (size_t)i * NN * 30);
    const float2* pC  = (const float2*)(C    + (size_t)i * NN);
    const float2* pD  = (const float2*)(D    + (size_t)i * NN);
    const float2* pS  = (const float2*)(S    + (size_t)i * NN);
    const float2* pM  = (const float2*)(Mk   + (size_t)i * NN);
    const float2* pXt = (const float2*)(g_Xt + (size_t)i * NN);
    float* outg = out + 1 + (size_t)i * NN;

    const int p  = tid;            // pair index 0..511
    const int j0 = 2 * p;

    int4 q0 = pIJ[p*3+0], q1 = pIJ[p*3+1], q2 = pIJ[p*3+2];
    int4 r0 = pF [p*3+0], r1 = pF [p*3+1], r2 = pF [p*3+2];
    float2 Cv = pC[p], Dv = pD[p], Sv = pS[p], Mv = pM[p], Xtv = pXt[p];

    float acc = 0.f;

    // ===== element 0 (column j0) =====
    {
        int4 u0 = pT[p*15+0], u1 = pT[p*15+1], u2 = pT[p*15+2], u3 = pT[p*15+3];
        int4 u4 = pT[p*15+4], u5 = pT[p*15+5], u6 = pT[p*15+6];
        int4 u7 = pT[p*15+7];

        float2 g0 = xg[q0.x], g1 = xg[q0.y], g2 = xg[q0.z],
               g3 = xg[q0.w], g4 = xg[q1.x], g5 = xg[q1.y];
        float locUp0 = ((g0.y + g1.y) + (g2.y + g3.y)) + (g4.y + g5.y);
        float skap = k0*g0.x + k1*g1.x + k2*g2.x + k3*g3.x + k4*g4.x + k5*g5.x;

        float f0 = xxs[r0.x], f1 = xxs[r0.y], f2 = xxs[r0.z],
              f3 = xxs[r0.w], f4 = xxs[r1.x], f5 = xxs[r1.y];
        float s0 = xxs[u0.x]+xxs[u0.y]+xxs[u0.z]+xxs[u0.w]+xxs[u1.x];
        float s1 = xxs[u1.y]+xxs[u1.z]+xxs[u1.w]+xxs[u2.x]+xxs[u2.y];
        float s2 = xxs[u2.z]+xxs[u2.w]+xxs[u3.x]+xxs[u3.y]+xxs[u3.z];
        float s3 = xxs[u3.w]+xxs[u4.x]+xxs[u4.y]+xxs[u4.z]+xxs[u4.w];
        float s4 = xxs[u5.x]+xxs[u5.y]+xxs[u5.z]+xxs[u5.w]+xxs[u6.x];
        float s5 = xxs[u6.y]+xxs[u6.z]+xxs[u6.w]+xxs[u7.x]+xxs[u7.y];
        float locUp1 = f0*s0 + f1*s1 + f2*s2 + f3*s3 + f4*s4 + f5*s5;

        float xv = xg[j0].x;
        float xt = Xtv.x;
        float x_ = 1.f - xv + EPSF;
        float lx_ = __logf(x_);
        float tmp0 = __expf(rls - lx_);
        float pr = lam + eta*Dv.x + nu*Cv.x + mu*Sv.x;
        float m  = Mv.x;
        float gm = (b1b0 + b2b1*locUp0 - b2v*locUp1)*tmp0
                 + (4.f*xt - 2.f)*pr + 100.f*(m - 1.f) + (4.f*skap - twoK);
        outg[j0] = __fdividef(1.f, 1.f + __expf(-gm*invt));
        float ent = xv*__logf(xv + EPSF) + x_*lx_;
        acc += m*( pr*(1.f + 4.f*xv*xt - 2.f*(xv + xt))
                 + (1.f - 2.f*xv)*(Ksum - 2.f*skap) - t*ent );
    }

    // ===== element 1 (column j0+1) =====
    {
        int4 u7  = pT[p*15+7];
        int4 u8  = pT[p*15+8],  u9  = pT[p*15+9],  u10 = pT[p*15+10];
        int4 u11 = pT[p*15+11], u12 = pT[p*15+12], u13 = pT[p*15+13], u14 = pT[p*15+14];

        float2 g0 = xg[q1.z], g1 = xg[q1.w], g2 = xg[q2.x],
               g3 = xg[q2.y], g4 = xg[q2.z], g5 = xg[q2.w];
        float locUp0 = ((g0.y + g1.y) + (g2.y + g3.y)) + (g4.y + g5.y);
        float skap = k0*g0.x + k1*g1.x + k2*g2.x + k3*g3.x + k4*g4.x + k5*g5.x;

        float f0 = xxs[r1.z], f1 = xxs[r1.w], f2 = xxs[r2.x],
              f3 = xxs[r2.y], f4 = xxs[r2.z], f5 = xxs[r2.w];
        float s0 = xxs[u7.z]+xxs[u7.w]+xxs[u8.x]+xxs[u8.y]+xxs[u8.z];
        float s1 = xxs[u8.w]+xxs[u9.x]+xxs[u9.y]+xxs[u9.z]+xxs[u9.w];
        float s2 = xxs[u10.x]+xxs[u10.y]+xxs[u10.z]+xxs[u10.w]+xxs[u11.x];
        float s3 = xxs[u11.y]+xxs[u11.z]+xxs[u11.w]+xxs[u12.x]+xxs[u12.y];
        float s4 = xxs[u12.z]+xxs[u12.w]+xxs[u13.x]+xxs[u13.y]+xxs[u13.z];
        float s5 = xxs[u13.w]+xxs[u14.x]+xxs[u14.y]+xxs[u14.z]+xxs[u14.w];
        float locUp1 = f0*s0 + f1*s1 + f2*s2 + f3*s3 + f4*s4 + f5*s5;

        float xv = xg[j0 + 1].x;
        float xt = Xtv.y;
        float x_ = 1.f - xv + EPSF;
        float lx_ = __logf(x_);
        float tmp0 = __expf(rls - lx_);
        float pr = lam + eta*Dv.y + nu*Cv.y + mu*Sv.y;
        float m  = Mv.y;
        float gm = (b1b0 + b2b1*locUp0 - b2v*locUp1)*tmp0
                 + (4.f*xt - 2.f)*pr + 100.f*(m - 1.f) + (4.f*skap - twoK);
        outg[j0 + 1] = __fdividef(1.f, 1.f + __expf(-gm*invt));
        float ent = xv*__logf(xv + EPSF) + x_*lx_;
        acc += m*( pr*(1.f + 4.f*xv*xt - 2.f*(xv + xt))
                 + (1.f - 2.f*xv)*(Ksum - 2.f*skap) - t*ent );
    }

    // ---- block reduction of acc; emit per-row partial ----
    __syncthreads();                 // protects s_spl
    float ar = wred(acc);
    if ((tid & 31) == 0) redC[tid >> 5] = ar;
    __syncthreads();
    if (tid == 0) {
        float tot = 0.f;
#pragma unroll
        for (int w = 0; w < 16; w++) tot += redC[w];
        float elbrow = (b0v + xxsumT*b1v + s_spl*b2v) * __expf(rls);
        g_part[i] = tot + elbrow;
        __threadfence();
        unsigned int old = atomicInc(&g_ctr, NN - 1);   // wraps to 0 after NN incs
        s_last = (old == NN - 1);
    }
    __syncthreads();

    // ---- last block: deterministic final sum in double ----
    if (s_last) {
        double dv = (double)g_part[tid] + (double)g_part[tid + 512];
        double dr = wredd(dv);
        if ((tid & 31) == 0) redD[tid >> 5] = dr;
        __syncthreads();
        if (tid == 0) {
            double tt = 0.0;
#pragma unroll
            for (int w = 0; w < 16; w++) tt += redD[w];
            out[0] = (float)tt;
        }
    }
}

// ---------------------------------------------------------------------------
extern "C" void kernel_launch(void* const* d_in, const int* in_sizes, int n_in,
                              void* d_out, int out_size) {
    const float* X    = (const float*)d_in[0];
    const float* T    = (const float*)d_in[1];
    const float* C    = (const float*)d_in[2];
    const float* D    = (const float*)d_in[3];
    const float* S    = (const float*)d_in[4];
    const float* Mk   = (const float*)d_in[5];
    const float* b0   = (const float*)d_in[6];
    const float* b1   = (const float*)d_in[7];
    const float* b2   = (const float*)d_in[8];
    const float* lam  = (const float*)d_in[9];
    const float* eta  = (const float*)d_in[10];
    const float* nu   = (const float*)d_in[11];
    const float* mu   = (const float*)d_in[12];
    const float* kap  = (const float*)d_in[13];
    const int*   iij  = (const int*)d_in[14];
    const int*   iijF = (const int*)d_in[15];
    const int*   iijT = (const int*)d_in[16];
    const int*   iiT  = (const int*)d_in[17];
    float* out = (float*)d_out;

    k_transpose<<<dim3(32, 32), dim3(32, 8)>>>(X);
    k_main<<<NN, 512>>>(X, C, D, S, Mk, T, b0, b1, b2, lam, eta, nu, mu, kap,
                        iij, iijF, iijT, iiT, out);
}

// round 4
// speedup vs baseline: 3.4306x; 2.5111x over previous
#include <cuda_runtime.h>

#define NN 1024
#define EPSF 1e-16f

// Static scratch (no allocation)
__device__ float g_Xt[NN * NN];      // X transpose
__device__ float g_part[NN];         // per-row elb partial
__device__ unsigned int g_ctr;       // block-done counter, wraps to 0

// ---------------------------------------------------------------------------
// Kernel 0: tiled transpose X -> g_Xt
// ---------------------------------------------------------------------------
__global__ void k_transpose(const float* __restrict__ X) {
    __shared__ float tile[32][33];
    int bx = blockIdx.x * 32, by = blockIdx.y * 32;
    int tx = threadIdx.x, ty = threadIdx.y;
#pragma unroll
    for (int r = 0; r < 32; r += 8)
        tile[ty + r][tx] = X[(by + ty + r) * NN + bx + tx];
    __syncthreads();
#pragma unroll
    for (int r = 0; r < 32; r += 8)
        g_Xt[(bx + ty + r) * NN + by + tx] = tile[tx][ty + r];
}

__device__ __forceinline__ float wred(float v) {
#pragma unroll
    for (int o = 16; o; o >>= 1) v += __shfl_down_sync(0xffffffffu, v, o);
    return v;
}
__device__ __forceinline__ float wrmin(float v) {
#pragma unroll
    for (int o = 16; o; o >>= 1) v = fminf(v, __shfl_down_sync(0xffffffffu, v, o));
    return v;
}
__device__ __forceinline__ double wredd(double v) {
#pragma unroll
    for (int o = 16; o; o >>= 1) v += __shfl_down_sync(0xffffffffu, v, o);
    return v;
}

// ---------------------------------------------------------------------------
// Kernel 1: fused main. Fast path when exp(rls - lx_) provably underflows to 0
// for every column of the row (then the locUp0/locUp1 term is exactly 0 in
// fp32, matching the reference), else full slow path.
// ---------------------------------------------------------------------------
__global__ void __launch_bounds__(512, 2) k_main(
    const float* __restrict__ X,
    const float* __restrict__ C,
    const float* __restrict__ D,
    const float* __restrict__ S,
    const float* __restrict__ Mk,
    const float* __restrict__ Tt,
    const float* __restrict__ B0, const float* __restrict__ B1, const float* __restrict__ B2,
    const float* __restrict__ LAM, const float* __restrict__ ETA,
    const float* __restrict__ NU, const float* __restrict__ MU,
    const float* __restrict__ KAP,
    const int* __restrict__ Iij,     // (N,N,6)
    const int* __restrict__ IijF,    // (N,N,6)
    const int* __restrict__ IijT,    // (N,N,6,5)
    const int* __restrict__ IiT,     // (N,21,2)
    float* __restrict__ out)
{
    int i = blockIdx.x, tid = threadIdx.x;
    __shared__ float  xs[NN];        // x
    __shared__ float  xxs[NN];       // x/(1-x+eps)
    __shared__ float  redA[16], redB[16], redC[16], redE[16];
    __shared__ double redD[16];
    __shared__ float  s_spl;
    __shared__ bool   s_last;

    // ---- prologue: load row i, build smem, local sums ----
    float lsum = 0.f, xxsum = 0.f, lmin = 1e30f;
    float2 xq = ((const float2*)(X + (size_t)i * NN))[tid];
    {
        float xv2[2] = {xq.x, xq.y};
#pragma unroll
        for (int k = 0; k < 2; k++) {
            int j = tid * 2 + k;
            float x  = xv2[k];
            float x_ = 1.f - x + EPSF;
            float lx = __logf(x_);
            float xx = __fdividef(x, x_);
            xs[j]  = x;
            xxs[j] = xx;
            lsum  += lx;
            xxsum += xx;
            lmin   = fminf(lmin, lx);
        }
    }
    __syncthreads();

    float wa = wred(lsum), wb = wred(xxsum), we = wrmin(lmin);
    if ((tid & 31) == 0) { redA[tid >> 5] = wa; redB[tid >> 5] = wb; redE[tid >> 5] = we; }
    __syncthreads();
    float rls = 0.f, xxsumT = 0.f, lminT = 1e30f;
#pragma unroll
    for (int w = 0; w < 16; w++) { rls += redA[w]; xxsumT += redB[w]; lminT = fminf(lminT, redE[w]); }

    // ---- iT: sum of 21 products xxs[a]*xxs[b] (warp 0 only) ----
    if (tid < 32) {
        float spl = 0.f;
        if (tid < 21) {
            int ka = IiT[((size_t)i * 21 + tid) * 2 + 0];
            int kb = IiT[((size_t)i * 21 + tid) * 2 + 1];
            spl = xxs[ka] * xxs[kb];
        }
        spl = wred(spl);
        if (tid == 0) s_spl = spl;
    }

    // ---- scalars ----
    float t  = Tt[0];
    float b0v = B0[0], b1v = B1[0], b2v = B2[0];
    float lam = LAM[0], eta = ETA[0], nu = NU[0], mu = MU[0];
    float k0 = KAP[0], k1 = KAP[1], k2 = KAP[2], k3 = KAP[3], k4 = KAP[4], k5 = KAP[5];
    float Ksum = ((k0 + k1) + (k2 + k3)) + (k4 + k5);
    float twoK = 2.f * Ksum;
    float b1b0 = b1v - b0v, b2b1 = b2v - b1v;
    float invt = __fdividef(1.f, t);

    const int4*   pIJ = (const int4*)(Iij  + (size_t)i * NN * 6);
    const float2* pC  = (const float2*)(C    + (size_t)i * NN);
    const float2* pD  = (const float2*)(D    + (size_t)i * NN);
    const float2* pS  = (const float2*)(S    + (size_t)i * NN);
    const float2* pM  = (const float2*)(Mk   + (size_t)i * NN);
    const float2* pXt = (const float2*)(g_Xt + (size_t)i * NN);
    float* outg = out + 1 + (size_t)i * NN;

    const int p  = tid;            // pair index 0..511
    const int j0 = 2 * p;

    int4 q0 = pIJ[p*3+0], q1 = pIJ[p*3+1], q2 = pIJ[p*3+2];
    float2 Cv = pC[p], Dv = pD[p], Sv = pS[p], Mv = pM[p], Xtv = pXt[p];

    float acc = 0.f;
    // max_j (rls - lx_j) = rls - min_j lx_j. If < -87, exp underflows to 0
    // (fp32, incl. subnormal leakage bounded < 1e-21 vs gamma O(1)).
    bool fastpath = (rls - lminT) < -87.0f;

    if (fastpath) {
        // ===== tmp0 == 0 for every element: locUp0/locUp1 term vanishes =====
        // element 0
        {
            float skap = k0*xs[q0.x] + k1*xs[q0.y] + k2*xs[q0.z]
                       + k3*xs[q0.w] + k4*xs[q1.x] + k5*xs[q1.y];
            float xv = xq.x, xt = Xtv.x;
            float x_ = 1.f - xv + EPSF;
            float lx_ = __logf(x_);
            float pr = lam + eta*Dv.x + nu*Cv.x + mu*Sv.x;
            float m  = Mv.x;
            float gm = (4.f*xt - 2.f)*pr + 100.f*(m - 1.f) + (4.f*skap - twoK);
            outg[j0] = __fdividef(1.f, 1.f + __expf(-gm*invt));
            float ent = xv*__logf(xv + EPSF) + x_*lx_;
            acc += m*( pr*(1.f + 4.f*xv*xt - 2.f*(xv + xt))
                     + (1.f - 2.f*xv)*(Ksum - 2.f*skap) - t*ent );
        }
        // element 1
        {
            float skap = k0*xs[q1.z] + k1*xs[q1.w] + k2*xs[q2.x]
                       + k3*xs[q2.y] + k4*xs[q2.z] + k5*xs[q2.w];
            float xv = xq.y, xt = Xtv.y;
            float x_ = 1.f - xv + EPSF;
            float lx_ = __logf(x_);
            float pr = lam + eta*Dv.y + nu*Cv.y + mu*Sv.y;
            float m  = Mv.y;
            float gm = (4.f*xt - 2.f)*pr + 100.f*(m - 1.f) + (4.f*skap - twoK);
            outg[j0 + 1] = __fdividef(1.f, 1.f + __expf(-gm*invt));
            float ent = xv*__logf(xv + EPSF) + x_*lx_;
            acc += m*( pr*(1.f + 4.f*xv*xt - 2.f*(xv + xt))
                     + (1.f - 2.f*xv)*(Ksum - 2.f*skap) - t*ent );
        }
    } else {
        // ===== full slow path (never taken for bench data, kept for rigor) =====
        const int4* pF = (const int4*)(IijF + (size_t)i * NN * 6);
        const int4* pT = (const int4*)(IijT + (size_t)i * NN * 30);
        int4 r0 = pF[p*3+0], r1 = pF[p*3+1], r2 = pF[p*3+2];

        // element 0
        {
            int4 u0 = pT[p*15+0], u1 = pT[p*15+1], u2 = pT[p*15+2], u3 = pT[p*15+3];
            int4 u4 = pT[p*15+4], u5 = pT[p*15+5], u6 = pT[p*15+6], u7 = pT[p*15+7];
            float locUp0 = ((xxs[q0.x] + xxs[q0.y]) + (xxs[q0.z] + xxs[q0.w]))
                         + (xxs[q1.x] + xxs[q1.y]);
            float skap = k0*xs[q0.x] + k1*xs[q0.y] + k2*xs[q0.z]
                       + k3*xs[q0.w] + k4*xs[q1.x] + k5*xs[q1.y];
            float f0 = xxs[r0.x], f1 = xxs[r0.y], f2 = xxs[r0.z],
                  f3 = xxs[r0.w], f4 = xxs[r1.x], f5 = xxs[r1.y];
            float s0 = xxs[u0.x]+xxs[u0.y]+xxs[u0.z]+xxs[u0.w]+xxs[u1.x];
            float s1 = xxs[u1.y]+xxs[u1.z]+xxs[u1.w]+xxs[u2.x]+xxs[u2.y];
            float s2 = xxs[u2.z]+xxs[u2.w]+xxs[u3.x]+xxs[u3.y]+xxs[u3.z];
            float s3 = xxs[u3.w]+xxs[u4.x]+xxs[u4.y]+xxs[u4.z]+xxs[u4.w];
            float s4 = xxs[u5.x]+xxs[u5.y]+xxs[u5.z]+xxs[u5.w]+xxs[u6.x];
            float s5 = xxs[u6.y]+xxs[u6.z]+xxs[u6.w]+xxs[u7.x]+xxs[u7.y];
            float locUp1 = f0*s0 + f1*s1 + f2*s2 + f3*s3 + f4*s4 + f5*s5;

            float xv = xq.x, xt = Xtv.x;
            float x_ = 1.f - xv + EPSF;
            float lx_ = __logf(x_);
            float tmp0 = __expf(rls - lx_);
            float pr = lam + eta*Dv.x + nu*Cv.x + mu*Sv.x;
            float m  = Mv.x;
            float gm = (b1b0 + b2b1*locUp0 - b2v*locUp1)*tmp0
                     + (4.f*xt - 2.f)*pr + 100.f*(m - 1.f) + (4.f*skap - twoK);
            outg[j0] = __fdividef(1.f, 1.f + __expf(-gm*invt));
            float ent = xv*__logf(xv + EPSF) + x_*lx_;
            acc += m*( pr*(1.f + 4.f*xv*xt - 2.f*(xv + xt))
                     + (1.f - 2.f*xv)*(Ksum - 2.f*skap) - t*ent );
        }
        // element 1
        {
            int4 u7  = pT[p*15+7];
            int4 u8  = pT[p*15+8],  u9  = pT[p*15+9],  u10 = pT[p*15+10];
            int4 u11 = pT[p*15+11], u12 = pT[p*15+12], u13 = pT[p*15+13], u14 = pT[p*15+14];
            float locUp0 = ((xxs[q1.z] + xxs[q1.w]) + (xxs[q2.x] + xxs[q2.y]))
                         + (xxs[q2.z] + xxs[q2.w]);
            float skap = k0*xs[q1.z] + k1*xs[q1.w] + k2*xs[q2.x]
                       + k3*xs[q2.y] + k4*xs[q2.z] + k5*xs[q2.w];
            float f0 = xxs[r1.z], f1 = xxs[r1.w], f2 = xxs[r2.x],
                  f3 = xxs[r2.y], f4 = xxs[r2.z], f5 = xxs[r2.w];
            float s0 = xxs[u7.z]+xxs[u7.w]+xxs[u8.x]+xxs[u8.y]+xxs[u8.z];
            float s1 = xxs[u8.w]+xxs[u9.x]+xxs[u9.y]+xxs[u9.z]+xxs[u9.w];
            float s2 = xxs[u10.x]+xxs[u10.y]+xxs[u10.z]+xxs[u10.w]+xxs[u11.x];
            float s3 = xxs[u11.y]+xxs[u11.z]+xxs[u11.w]+xxs[u12.x]+xxs[u12.y];
            float s4 = xxs[u12.z]+xxs[u12.w]+xxs[u13.x]+xxs[u13.y]+xxs[u13.z];
            float s5 = xxs[u13.w]+xxs[u14.x]+xxs[u14.y]+xxs[u14.z]+xxs[u14.w];
            float locUp1 = f0*s0 + f1*s1 + f2*s2 + f3*s3 + f4*s4 + f5*s5;

            float xv = xq.y, xt = Xtv.y;
            float x_ = 1.f - xv + EPSF;
            float lx_ = __logf(x_);
            float tmp0 = __expf(rls - lx_);
            float pr = lam + eta*Dv.y + nu*Cv.y + mu*Sv.y;
            float m  = Mv.y;
            float gm = (b1b0 + b2b1*locUp0 - b2v*locUp1)*tmp0
                     + (4.f*xt - 2.f)*pr + 100.f*(m - 1.f) + (4.f*skap - twoK);
            outg[j0 + 1] = __fdividef(1.f, 1.f + __expf(-gm*invt));
            float ent = xv*__logf(xv + EPSF) + x_*lx_;
            acc += m*( pr*(1.f + 4.f*xv*xt - 2.f*(xv + xt))
                     + (1.f - 2.f*xv)*(Ksum - 2.f*skap) - t*ent );
        }
    }

    // ---- block reduction of acc; emit per-row partial ----
    __syncthreads();                 // protects s_spl
    float ar = wred(acc);
    if ((tid & 31) == 0) redC[tid >> 5] = ar;
    __syncthreads();
    if (tid == 0) {
        float tot = 0.f;
#pragma unroll
        for (int w = 0; w < 16; w++) tot += redC[w];
        float elbrow = (b0v + xxsumT*b1v + s_spl*b2v) * __expf(rls);
        g_part[i] = tot + elbrow;
        __threadfence();
        unsigned int old = atomicInc(&g_ctr, NN - 1);   // wraps to 0 after NN incs
        s_last = (old == NN - 1);
    }
    __syncthreads();

    // ---- last block: deterministic final sum in double ----
    if (s_last) {
        double dv = (double)g_part[tid] + (double)g_part[tid + 512];
        double dr = wredd(dv);
        if ((tid & 31) == 0) redD[tid >> 5] = dr;
        __syncthreads();
        if (tid == 0) {
            double tt = 0.0;
#pragma unroll
            for (int w = 0; w < 16; w++) tt += redD[w];
            out[0] = (float)tt;
        }
    }
}

// ---------------------------------------------------------------------------
extern "C" void kernel_launch(void* const* d_in, const int* in_sizes, int n_in,
                              void* d_out, int out_size) {
    const float* X    = (const float*)d_in[0];
    const float* T    = (const float*)d_in[1];
    const float* C    = (const float*)d_in[2];
    const float* D    = (const float*)d_in[3];
    const float* S    = (const float*)d_in[4];
    const float* Mk   = (const float*)d_in[5];
    const float* b0   = (const float*)d_in[6];
    const float* b1   = (const float*)d_in[7];
    const float* b2   = (const float*)d_in[8];
    const float* lam  = (const float*)d_in[9];
    const float* eta  = (const float*)d_in[10];
    const float* nu   = (const float*)d_in[11];
    const float* mu   = (const float*)d_in[12];
    const float* kap  = (const float*)d_in[13];
    const int*   iij  = (const int*)d_in[14];
    const int*   iijF = (const int*)d_in[15];
    const int*   iijT = (const int*)d_in[16];
    const int*   iiT  = (const int*)d_in[17];
    float* out = (float*)d_out;

    k_transpose<<<dim3(32, 32), dim3(32, 8)>>>(X);
    k_main<<<NN, 512>>>(X, C, D, S, Mk, T, b0, b1, b2, lam, eta, nu, mu, kap,
                        iij, iijF, iijT, iiT, out);
}

// round 5
// speedup vs baseline: 3.7199x; 1.0843x over previous
#include <cuda_runtime.h>

#define NN 1024
#define EPSF 1e-16f

// Static scratch (no allocation)
__device__ float g_Xt[NN * NN];      // X transpose
__device__ float g_part[NN];         // per-row elb partial
__device__ unsigned int g_ctr;       // block-done counter, wraps to 0

// ---------------------------------------------------------------------------
// Kernel 0: tiled transpose X -> g_Xt
// ---------------------------------------------------------------------------
__global__ void k_transpose(const float* __restrict__ X) {
    __shared__ float tile[32][33];
    int bx = blockIdx.x * 32, by = blockIdx.y * 32;
    int tx = threadIdx.x, ty = threadIdx.y;
#pragma unroll
    for (int r = 0; r < 32; r += 8)
        tile[ty + r][tx] = X[(by + ty + r) * NN + bx + tx];
    __syncthreads();
#pragma unroll
    for (int r = 0; r < 32; r += 8)
        g_Xt[(bx + ty + r) * NN + by + tx] = tile[tx][ty + r];
}

__device__ __forceinline__ float wred(float v) {
#pragma unroll
    for (int o = 16; o; o >>= 1) v += __shfl_down_sync(0xffffffffu, v, o);
    return v;
}
__device__ __forceinline__ float wrmin(float v) {
#pragma unroll
    for (int o = 16; o; o >>= 1) v = fminf(v, __shfl_down_sync(0xffffffffu, v, o));
    return v;
}
__device__ __forceinline__ double wredd(double v) {
#pragma unroll
    for (int o = 16; o; o >>= 1) v += __shfl_down_sync(0xffffffffu, v, o);
    return v;
}

// ---------------------------------------------------------------------------
// Kernel 1: fused main. Fast path when exp(rls - lx_) provably underflows to 0
// for every column (then the tmp0 term AND the exp(rls) elbrow term are
// exactly 0 in fp32, matching the reference). Slow path is full-fidelity.
// ---------------------------------------------------------------------------
__global__ void __launch_bounds__(512, 3) k_main(
    const float* __restrict__ X,
    const float* __restrict__ C,
    const float* __restrict__ D,
    const float* __restrict__ S,
    const float* __restrict__ Mk,
    const float* __restrict__ Tt,
    const float* __restrict__ B0, const float* __restrict__ B1, const float* __restrict__ B2,
    const float* __restrict__ LAM, const float* __restrict__ ETA,
    const float* __restrict__ NU, const float* __restrict__ MU,
    const float* __restrict__ KAP,
    const int* __restrict__ Iij,     // (N,N,6)
    const int* __restrict__ IijF,    // (N,N,6)
    const int* __restrict__ IijT,    // (N,N,6,5)
    const int* __restrict__ IiT,     // (N,21,2)
    float* __restrict__ out)
{
    int i = blockIdx.x, tid = threadIdx.x;
    __shared__ float  xs[NN];        // x
    __shared__ float  xxs[NN];       // x/(1-x+eps)  (slow path only)
    __shared__ float  redA[16], redE[16], redC[16];
    __shared__ double redD[16];
    __shared__ float  s_spl;
    __shared__ bool   s_last;

    // ---- prologue: load row i, store xs, reduce (lsum, lmin) ----
    float2 xq = ((const float2*)(X + (size_t)i * NN))[tid];
    float x_0 = 1.f - xq.x + EPSF;
    float x_1 = 1.f - xq.y + EPSF;
    float lx0 = __logf(x_0);
    float lx1 = __logf(x_1);
    xs[2 * tid]     = xq.x;
    xs[2 * tid + 1] = xq.y;
    float lsum = lx0 + lx1;
    float lmin = fminf(lx0, lx1);
    __syncthreads();

    float wa = wred(lsum), we = wrmin(lmin);
    if ((tid & 31) == 0) { redA[tid >> 5] = wa; redE[tid >> 5] = we; }
    __syncthreads();
    float rls = 0.f, lminT = 1e30f;
#pragma unroll
    for (int w = 0; w < 16; w++) { rls += redA[w]; lminT = fminf(lminT, redE[w]); }

    // ---- scalars (fast-path set only) ----
    float t   = Tt[0];
    float lam = LAM[0], eta = ETA[0], nu = NU[0], mu = MU[0];
    float k0 = KAP[0], k1 = KAP[1], k2 = KAP[2], k3 = KAP[3], k4 = KAP[4], k5 = KAP[5];
    float Ksum = ((k0 + k1) + (k2 + k3)) + (k4 + k5);
    float twoK = 2.f * Ksum;
    float invt = __fdividef(1.f, t);

    const int4*   pIJ = (const int4*)(Iij  + (size_t)i * NN * 6);
    const float2* pC  = (const float2*)(C    + (size_t)i * NN);
    const float2* pD  = (const float2*)(D    + (size_t)i * NN);
    const float2* pS  = (const float2*)(S    + (size_t)i * NN);
    const float2* pM  = (const float2*)(Mk   + (size_t)i * NN);
    const float2* pXt = (const float2*)(g_Xt + (size_t)i * NN);
    float* outg = out + 1 + (size_t)i * NN;

    const int p  = tid;            // pair index 0..511
    const int j0 = 2 * p;

    int4 q0 = pIJ[p*3+0], q1 = pIJ[p*3+1], q2 = pIJ[p*3+2];
    float2 Cv = pC[p], Dv = pD[p], Sv = pS[p], Mv = pM[p], Xtv = pXt[p];

    float acc = 0.f;
    float elbrow = 0.f;
    // max_j (rls - lx_j) = rls - min_j lx_j. If < -87, exp underflows to 0
    // (and since lminT <= ~1e-16, rls < -87 too, so exp(rls) == 0 as well).
    bool fastpath = (rls - lminT) < -87.0f;

    if (fastpath) {
        // ===== tmp0 == 0 and exp(rls) == 0: only skap/pair/entropy remain =====
        // element 0
        {
            float skap = k0*xs[q0.x] + k1*xs[q0.y] + k2*xs[q0.z]
                       + k3*xs[q0.w] + k4*xs[q1.x] + k5*xs[q1.y];
            float xv = xq.x, xt = Xtv.x;
            float pr = lam + eta*Dv.x + nu*Cv.x + mu*Sv.x;
            float m  = Mv.x;
            float gm = (4.f*xt - 2.f)*pr + 100.f*(m - 1.f) + (4.f*skap - twoK);
            outg[j0] = __fdividef(1.f, 1.f + __expf(-gm*invt));
            float ent = xv*__logf(xv + EPSF) + x_0*lx0;
            acc += m*( pr*(1.f + 4.f*xv*xt - 2.f*(xv + xt))
                     + (1.f - 2.f*xv)*(Ksum - 2.f*skap) - t*ent );
        }
        // element 1
        {
            float skap = k0*xs[q1.z] + k1*xs[q1.w] + k2*xs[q2.x]
                       + k3*xs[q2.y] + k4*xs[q2.z] + k5*xs[q2.w];
            float xv = xq.y, xt = Xtv.y;
            float pr = lam + eta*Dv.y + nu*Cv.y + mu*Sv.y;
            float m  = Mv.y;
            float gm = (4.f*xt - 2.f)*pr + 100.f*(m - 1.f) + (4.f*skap - twoK);
            outg[j0 + 1] = __fdividef(1.f, 1.f + __expf(-gm*invt));
            float ent = xv*__logf(xv + EPSF) + x_1*lx1;
            acc += m*( pr*(1.f + 4.f*xv*xt - 2.f*(xv + xt))
                     + (1.f - 2.f*xv)*(Ksum - 2.f*skap) - t*ent );
        }
    } else {
        // ===== full slow path (never taken for bench data, kept for rigor) =====
        // build xxs (uniform branch: all threads participate)
        {
            xxs[2 * tid]     = __fdividef(xq.x, x_0);
            xxs[2 * tid + 1] = __fdividef(xq.y, x_1);
        }
        __syncthreads();

        // xxsum reduction
        float xxl = xxs[2 * tid] + xxs[2 * tid + 1];
        float wb = wred(xxl);
        if ((tid & 31) == 0) redC[tid >> 5] = wb;
        __syncthreads();
        float xxsumT = 0.f;
#pragma unroll
        for (int w = 0; w < 16; w++) xxsumT += redC[w];

        // iT: sum of 21 products (warp 0)
        if (tid < 32) {
            float spl = 0.f;
            if (tid < 21) {
                int ka = IiT[((size_t)i * 21 + tid) * 2 + 0];
                int kb = IiT[((size_t)i * 21 + tid) * 2 + 1];
                spl = xxs[ka] * xxs[kb];
            }
            spl = wred(spl);
            if (tid == 0) s_spl = spl;
        }
        __syncthreads();

        float b0v = B0[0], b1v = B1[0], b2v = B2[0];
        float b1b0 = b1v - b0v, b2b1 = b2v - b1v;
        elbrow = (b0v + xxsumT*b1v + s_spl*b2v) * __expf(rls);

        const int4* pF = (const int4*)(IijF + (size_t)i * NN * 6);
        const int4* pT = (const int4*)(IijT + (size_t)i * NN * 30);
        int4 r0 = pF[p*3+0], r1 = pF[p*3+1], r2 = pF[p*3+2];

        // element 0
        {
            int4 u0 = pT[p*15+0], u1 = pT[p*15+1], u2 = pT[p*15+2], u3 = pT[p*15+3];
            int4 u4 = pT[p*15+4], u5 = pT[p*15+5], u6 = pT[p*15+6], u7 = pT[p*15+7];
            float locUp0 = ((xxs[q0.x] + xxs[q0.y]) + (xxs[q0.z] + xxs[q0.w]))
                         + (xxs[q1.x] + xxs[q1.y]);
            float skap = k0*xs[q0.x] + k1*xs[q0.y] + k2*xs[q0.z]
                       + k3*xs[q0.w] + k4*xs[q1.x] + k5*xs[q1.y];
            float f0 = xxs[r0.x], f1 = xxs[r0.y], f2 = xxs[r0.z],
                  f3 = xxs[r0.w], f4 = xxs[r1.x], f5 = xxs[r1.y];
            float s0 = xxs[u0.x]+xxs[u0.y]+xxs[u0.z]+xxs[u0.w]+xxs[u1.x];
            float s1 = xxs[u1.y]+xxs[u1.z]+xxs[u1.w]+xxs[u2.x]+xxs[u2.y];
            float s2 = xxs[u2.z]+xxs[u2.w]+xxs[u3.x]+xxs[u3.y]+xxs[u3.z];
            float s3 = xxs[u3.w]+xxs[u4.x]+xxs[u4.y]+xxs[u4.z]+xxs[u4.w];
            float s4 = xxs[u5.x]+xxs[u5.y]+xxs[u5.z]+xxs[u5.w]+xxs[u6.x];
            float s5 = xxs[u6.y]+xxs[u6.z]+xxs[u6.w]+xxs[u7.x]+xxs[u7.y];
            float locUp1 = f0*s0 + f1*s1 + f2*s2 + f3*s3 + f4*s4 + f5*s5;

            float xv = xq.x, xt = Xtv.x;
            float tmp0 = __expf(rls - lx0);
            float pr = lam + eta*Dv.x + nu*Cv.x + mu*Sv.x;
            float m  = Mv.x;
            float gm = (b1b0 + b2b1*locUp0 - b2v*locUp1)*tmp0
                     + (4.f*xt - 2.f)*pr + 100.f*(m - 1.f) + (4.f*skap - twoK);
            outg[j0] = __fdividef(1.f, 1.f + __expf(-gm*invt));
            float ent = xv*__logf(xv + EPSF) + x_0*lx0;
            acc += m*( pr*(1.f + 4.f*xv*xt - 2.f*(xv + xt))
                     + (1.f - 2.f*xv)*(Ksum - 2.f*skap) - t*ent );
        }
        // element 1
        {
            int4 u7  = pT[p*15+7];
            int4 u8  = pT[p*15+8],  u9  = pT[p*15+9],  u10 = pT[p*15+10];
            int4 u11 = pT[p*15+11], u12 = pT[p*15+12], u13 = pT[p*15+13], u14 = pT[p*15+14];
            float locUp0 = ((xxs[q1.z] + xxs[q1.w]) + (xxs[q2.x] + xxs[q2.y]))
                         + (xxs[q2.z] + xxs[q2.w]);
            float skap = k0*xs[q1.z] + k1*xs[q1.w] + k2*xs[q2.x]
                       + k3*xs[q2.y] + k4*xs[q2.z] + k5*xs[q2.w];
            float f0 = xxs[r1.z], f1 = xxs[r1.w], f2 = xxs[r2.x],
                  f3 = xxs[r2.y], f4 = xxs[r2.z], f5 = xxs[r2.w];
            float s0 = xxs[u7.z]+xxs[u7.w]+xxs[u8.x]+xxs[u8.y]+xxs[u8.z];
            float s1 = xxs[u8.w]+xxs[u9.x]+xxs[u9.y]+xxs[u9.z]+xxs[u9.w];
            float s2 = xxs[u10.x]+xxs[u10.y]+xxs[u10.z]+xxs[u10.w]+xxs[u11.x];
            float s3 = xxs[u11.y]+xxs[u11.z]+xxs[u11.w]+xxs[u12.x]+xxs[u12.y];
            float s4 = xxs[u12.z]+xxs[u12.w]+xxs[u13.x]+xxs[u13.y]+xxs[u13.z];
            float s5 = xxs[u13.w]+xxs[u14.x]+xxs[u14.y]+xxs[u14.z]+xxs[u14.w];
            float locUp1 = f0*s0 + f1*s1 + f2*s2 + f3*s3 + f4*s4 + f5*s5;

            float xv = xq.y, xt = Xtv.y;
            float tmp0 = __expf(rls - lx1);
            float pr = lam + eta*Dv.y + nu*Cv.y + mu*Sv.y;
            float m  = Mv.y;
            float gm = (b1b0 + b2b1*locUp0 - b2v*locUp1)*tmp0
                     + (4.f*xt - 2.f)*pr + 100.f*(m - 1.f) + (4.f*skap - twoK);
            outg[j0 + 1] = __fdividef(1.f, 1.f + __expf(-gm*invt));
            float ent = xv*__logf(xv + EPSF) + x_1*lx1;
            acc += m*( pr*(1.f + 4.f*xv*xt - 2.f*(xv + xt))
                     + (1.f - 2.f*xv)*(Ksum - 2.f*skap) - t*ent );
        }
        __syncthreads();
    }

    // ---- block reduction of acc; emit per-row partial ----
    float ar = wred(acc);
    if ((tid & 31) == 0) redC[tid >> 5] = ar;
    __syncthreads();
    if (tid == 0) {
        float tot = 0.f;
#pragma unroll
        for (int w = 0; w < 16; w++) tot += redC[w];
        g_part[i] = tot + elbrow;
        __threadfence();
        unsigned int old = atomicInc(&g_ctr, NN - 1);   // wraps to 0 after NN incs
        s_last = (old == NN - 1);
    }
    __syncthreads();

    // ---- last block: deterministic final sum in double ----
    if (s_last) {
        double dv = (double)g_part[tid] + (double)g_part[tid + 512];
        double dr = wredd(dv);
        if ((tid & 31) == 0) redD[tid >> 5] = dr;
        __syncthreads();
        if (tid == 0) {
            double tt = 0.0;
#pragma unroll
            for (int w = 0; w < 16; w++) tt += redD[w];
            out[0] = (float)tt;
        }
    }
}

// ---------------------------------------------------------------------------
extern "C" void kernel_launch(void* const* d_in, const int* in_sizes, int n_in,
                              void* d_out, int out_size) {
    const float* X    = (const float*)d_in[0];
    const float* T    = (const float*)d_in[1];
    const float* C    = (const float*)d_in[2];
    const float* D    = (const float*)d_in[3];
    const float* S    = (const float*)d_in[4];
    const float* Mk   = (const float*)d_in[5];
    const float* b0   = (const float*)d_in[6];
    const float* b1   = (const float*)d_in[7];
    const float* b2   = (const float*)d_in[8];
    const float* lam  = (const float*)d_in[9];
    const float* eta  = (const float*)d_in[10];
    const float* nu   = (const float*)d_in[11];
    const float* mu   = (const float*)d_in[12];
    const float* kap  = (const float*)d_in[13];
    const int*   iij  = (const int*)d_in[14];
    const int*   iijF = (const int*)d_in[15];
    const int*   iijT = (const int*)d_in[16];
    const int*   iiT  = (const int*)d_in[17];
    float* out = (float*)d_out;

    k_transpose<<<dim3(32, 32), dim3(32, 8)>>>(X);
    k_main<<<NN, 512>>>(X, C, D, S, Mk, T, b0, b1, b2, lam, eta, nu, mu, kap,
                        iij, iijF, iijT, iiT, out);
}

// round 6
// speedup vs baseline: 3.7710x; 1.0137x over previous
#include <cuda_runtime.h>

#define NN 1024
#define EPSF 1e-16f

// Static scratch (no allocation)
__device__ float g_Xt[NN * NN];          // X transpose
__device__ float g_rls_part[NN * 32];    // per-(row, col-tile) partial of sum log(1-x)
__device__ float g_part[NN];             // per-row elb partial
__device__ unsigned int g_ctr;           // block-done counter, wraps to 0

__device__ __forceinline__ float wred(float v) {
#pragma unroll
    for (int o = 16; o; o >>= 1) v += __shfl_down_sync(0xffffffffu, v, o);
    return v;
}
__device__ __forceinline__ double wredd(double v) {
#pragma unroll
    for (int o = 16; o; o >>= 1) v += __shfl_down_sync(0xffffffffu, v, o);
    return v;
}

// ---------------------------------------------------------------------------
// Kernel 0: tiled transpose X -> g_Xt, plus deterministic per-(row,tile)
// partials of sum_j log(1-x+eps) into g_rls_part.
// ---------------------------------------------------------------------------
__global__ void k_transpose(const float* __restrict__ X) {
    __shared__ float tile[32][33];
    int bx = blockIdx.x * 32, by = blockIdx.y * 32;
    int tx = threadIdx.x, ty = threadIdx.y;
#pragma unroll
    for (int r = 0; r < 32; r += 8) {
        float x = X[(by + ty + r) * NN + bx + tx];
        tile[ty + r][tx] = x;
        // deterministic 32-wide partial of log(1-x+eps) for this row chunk
        float lx = __logf(1.f - x + EPSF);
        float s = wred(lx);
        if (tx == 0) g_rls_part[(by + ty + r) * 32 + blockIdx.x] = s;
    }
    __syncthreads();
#pragma unroll
    for (int r = 0; r < 32; r += 8)
        g_Xt[(bx + ty + r) * NN + by + tx] = tile[tx][ty + r];
}

// ---------------------------------------------------------------------------
// Kernel 1: fused main. Fast path when rls < -125 (then rls - lmin < -87
// because lmin >= log(EPSF) = -36.85, so exp(rls - lx) underflows to 0 for
// every column AND exp(rls) == 0 — matching fp32 reference exactly).
// ---------------------------------------------------------------------------
__global__ void __launch_bounds__(512, 3) k_main(
    const float* __restrict__ X,
    const float* __restrict__ C,
    const float* __restrict__ D,
    const float* __restrict__ S,
    const float* __restrict__ Mk,
    const float* __restrict__ Tt,
    const float* __restrict__ B0, const float* __restrict__ B1, const float* __restrict__ B2,
    const float* __restrict__ LAM, const float* __restrict__ ETA,
    const float* __restrict__ NU, const float* __restrict__ MU,
    const float* __restrict__ KAP,
    const int* __restrict__ Iij,     // (N,N,6)
    const int* __restrict__ IijF,    // (N,N,6)
    const int* __restrict__ IijT,    // (N,N,6,5)
    const int* __restrict__ IiT,     // (N,21,2)
    float* __restrict__ out)
{
    int i = blockIdx.x, tid = threadIdx.x;
    __shared__ float  xs[NN];        // x
    __shared__ float  xxs[NN];       // x/(1-x+eps)  (slow path only)
    __shared__ float  redC[16];
    __shared__ double redD[16];
    __shared__ float  s_rls;
    __shared__ float  s_spl;
    __shared__ bool   s_last;

    // ---- prologue: load row i, warp0 sums the precomputed rls partials ----
    float2 xq = ((const float2*)(X + (size_t)i * NN))[tid];
    float x_0 = 1.f - xq.x + EPSF;
    float x_1 = 1.f - xq.y + EPSF;
    float lx0 = __logf(x_0);
    float lx1 = __logf(x_1);
    xs[2 * tid]     = xq.x;
    xs[2 * tid + 1] = xq.y;
    if (tid < 32) {
        float v = wred(g_rls_part[i * 32 + tid]);
        if (tid == 0) s_rls = v;
    }
    __syncthreads();
    float rls = s_rls;

    // ---- scalars (fast-path set only) ----
    float t   = Tt[0];
    float lam = LAM[0], eta = ETA[0], nu = NU[0], mu = MU[0];
    float k0 = KAP[0], k1 = KAP[1], k2 = KAP[2], k3 = KAP[3], k4 = KAP[4], k5 = KAP[5];
    float Ksum = ((k0 + k1) + (k2 + k3)) + (k4 + k5);
    float twoK = 2.f * Ksum;
    float invt = __fdividef(1.f, t);

    const int4*   pIJ = (const int4*)(Iij  + (size_t)i * NN * 6);
    const float2* pC  = (const float2*)(C    + (size_t)i * NN);
    const float2* pD  = (const float2*)(D    + (size_t)i * NN);
    const float2* pS  = (const float2*)(S    + (size_t)i * NN);
    const float2* pM  = (const float2*)(Mk   + (size_t)i * NN);
    const float2* pXt = (const float2*)(g_Xt + (size_t)i * NN);
    float* outg = out + 1 + (size_t)i * NN;

    const int p  = tid;            // pair index 0..511
    const int j0 = 2 * p;

    int4 q0 = __ldcs(pIJ + p*3+0), q1 = __ldcs(pIJ + p*3+1), q2 = __ldcs(pIJ + p*3+2);
    float2 Cv = __ldcs(pC + p), Dv = __ldcs(pD + p), Sv = __ldcs(pS + p),
           Mv = __ldcs(pM + p), Xtv = __ldcs(pXt + p);

    float acc = 0.f;
    float elbrow = 0.f;
    bool fastpath = rls < -125.0f;

    if (fastpath) {
        // ===== tmp0 == 0 and exp(rls) == 0: only skap/pair/entropy remain =====
        // element 0
        {
            float skap = k0*xs[q0.x] + k1*xs[q0.y] + k2*xs[q0.z]
                       + k3*xs[q0.w] + k4*xs[q1.x] + k5*xs[q1.y];
            float xv = xq.x, xt = Xtv.x;
            float pr = lam + eta*Dv.x + nu*Cv.x + mu*Sv.x;
            float m  = Mv.x;
            float gm = (4.f*xt - 2.f)*pr + 100.f*(m - 1.f) + (4.f*skap - twoK);
            __stcs(outg + j0, __fdividef(1.f, 1.f + __expf(-gm*invt)));
            float ent = xv*__logf(xv + EPSF) + x_0*lx0;
            acc += m*( pr*(1.f + 4.f*xv*xt - 2.f*(xv + xt))
                     + (1.f - 2.f*xv)*(Ksum - 2.f*skap) - t*ent );
        }
        // element 1
        {
            float skap = k0*xs[q1.z] + k1*xs[q1.w] + k2*xs[q2.x]
                       + k3*xs[q2.y] + k4*xs[q2.z] + k5*xs[q2.w];
            float xv = xq.y, xt = Xtv.y;
            float pr = lam + eta*Dv.y + nu*Cv.y + mu*Sv.y;
            float m  = Mv.y;
            float gm = (4.f*xt - 2.f)*pr + 100.f*(m - 1.f) + (4.f*skap - twoK);
            __stcs(outg + j0 + 1, __fdividef(1.f, 1.f + __expf(-gm*invt)));
            float ent = xv*__logf(xv + EPSF) + x_1*lx1;
            acc += m*( pr*(1.f + 4.f*xv*xt - 2.f*(xv + xt))
                     + (1.f - 2.f*xv)*(Ksum - 2.f*skap) - t*ent );
        }
    } else {
        // ===== full slow path (never taken for bench data, kept for rigor) =====
        xxs[2 * tid]     = __fdividef(xq.x, x_0);
        xxs[2 * tid + 1] = __fdividef(xq.y, x_1);
        __syncthreads();

        // xxsum reduction
        float xxl = xxs[2 * tid] + xxs[2 * tid + 1];
        float wb = wred(xxl);
        if ((tid & 31) == 0) redC[tid >> 5] = wb;
        __syncthreads();
        float xxsumT = 0.f;
#pragma unroll
        for (int w = 0; w < 16; w++) xxsumT += redC[w];

        // iT: sum of 21 products (warp 0)
        if (tid < 32) {
            float spl = 0.f;
            if (tid < 21) {
                int ka = IiT[((size_t)i * 21 + tid) * 2 + 0];
                int kb = IiT[((size_t)i * 21 + tid) * 2 + 1];
                spl = xxs[ka] * xxs[kb];
            }
            spl = wred(spl);
            if (tid == 0) s_spl = spl;
        }
        __syncthreads();

        float b0v = B0[0], b1v = B1[0], b2v = B2[0];
        float b1b0 = b1v - b0v, b2b1 = b2v - b1v;
        elbrow = (b0v + xxsumT*b1v + s_spl*b2v) * __expf(rls);

        const int4* pF = (const int4*)(IijF + (size_t)i * NN * 6);
        const int4* pT = (const int4*)(IijT + (size_t)i * NN * 30);
        int4 r0 = pF[p*3+0], r1 = pF[p*3+1], r2 = pF[p*3+2];

        // element 0
        {
            int4 u0 = pT[p*15+0], u1 = pT[p*15+1], u2 = pT[p*15+2], u3 = pT[p*15+3];
            int4 u4 = pT[p*15+4], u5 = pT[p*15+5], u6 = pT[p*15+6], u7 = pT[p*15+7];
            float locUp0 = ((xxs[q0.x] + xxs[q0.y]) + (xxs[q0.z] + xxs[q0.w]))
                         + (xxs[q1.x] + xxs[q1.y]);
            float skap = k0*xs[q0.x] + k1*xs[q0.y] + k2*xs[q0.z]
                       + k3*xs[q0.w] + k4*xs[q1.x] + k5*xs[q1.y];
            float f0 = xxs[r0.x], f1 = xxs[r0.y], f2 = xxs[r0.z],
                  f3 = xxs[r0.w], f4 = xxs[r1.x], f5 = xxs[r1.y];
            float s0 = xxs[u0.x]+xxs[u0.y]+xxs[u0.z]+xxs[u0.w]+xxs[u1.x];
            float s1 = xxs[u1.y]+xxs[u1.z]+xxs[u1.w]+xxs[u2.x]+xxs[u2.y];
            float s2 = xxs[u2.z]+xxs[u2.w]+xxs[u3.x]+xxs[u3.y]+xxs[u3.z];
            float s3 = xxs[u3.w]+xxs[u4.x]+xxs[u4.y]+xxs[u4.z]+xxs[u4.w];
            float s4 = xxs[u5.x]+xxs[u5.y]+xxs[u5.z]+xxs[u5.w]+xxs[u6.x];
            float s5 = xxs[u6.y]+xxs[u6.z]+xxs[u6.w]+xxs[u7.x]+xxs[u7.y];
            float locUp1 = f0*s0 + f1*s1 + f2*s2 + f3*s3 + f4*s4 + f5*s5;

            float xv = xq.x, xt = Xtv.x;
            float tmp0 = __expf(rls - lx0);
            float pr = lam + eta*Dv.x + nu*Cv.x + mu*Sv.x;
            float m  = Mv.x;
            float gm = (b1b0 + b2b1*locUp0 - b2v*locUp1)*tmp0
                     + (4.f*xt - 2.f)*pr + 100.f*(m - 1.f) + (4.f*skap - twoK);
            outg[j0] = __fdividef(1.f, 1.f + __expf(-gm*invt));
            float ent = xv*__logf(xv + EPSF) + x_0*lx0;
            acc += m*( pr*(1.f + 4.f*xv*xt - 2.f*(xv + xt))
                     + (1.f - 2.f*xv)*(Ksum - 2.f*skap) - t*ent );
        }
        // element 1
        {
            int4 u7  = pT[p*15+7];
            int4 u8  = pT[p*15+8],  u9  = pT[p*15+9],  u10 = pT[p*15+10];
            int4 u11 = pT[p*15+11], u12 = pT[p*15+12], u13 = pT[p*15+13], u14 = pT[p*15+14];
            float locUp0 = ((xxs[q1.z] + xxs[q1.w]) + (xxs[q2.x] + xxs[q2.y]))
                         + (xxs[q2.z] + xxs[q2.w]);
            float skap = k0*xs[q1.z] + k1*xs[q1.w] + k2*xs[q2.x]
                       + k3*xs[q2.y] + k4*xs[q2.z] + k5*xs[q2.w];
            float f0 = xxs[r1.z], f1 = xxs[r1.w], f2 = xxs[r2.x],
                  f3 = xxs[r2.y], f4 = xxs[r2.z], f5 = xxs[r2.w];
            float s0 = xxs[u7.z]+xxs[u7.w]+xxs[u8.x]+xxs[u8.y]+xxs[u8.z];
            float s1 = xxs[u8.w]+xxs[u9.x]+xxs[u9.y]+xxs[u9.z]+xxs[u9.w];
            float s2 = xxs[u10.x]+xxs[u10.y]+xxs[u10.z]+xxs[u10.w]+xxs[u11.x];
            float s3 = xxs[u11.y]+xxs[u11.z]+xxs[u11.w]+xxs[u12.x]+xxs[u12.y];
            float s4 = xxs[u12.z]+xxs[u12.w]+xxs[u13.x]+xxs[u13.y]+xxs[u13.z];
            float s5 = xxs[u13.w]+xxs[u14.x]+xxs[u14.y]+xxs[u14.z]+xxs[u14.w];
            float locUp1 = f0*s0 + f1*s1 + f2*s2 + f3*s3 + f4*s4 + f5*s5;

            float xv = xq.y, xt = Xtv.y;
            float tmp0 = __expf(rls - lx1);
            float pr = lam + eta*Dv.y + nu*Cv.y + mu*Sv.y;
            float m  = Mv.y;
            float gm = (b1b0 + b2b1*locUp0 - b2v*locUp1)*tmp0
                     + (4.f*xt - 2.f)*pr + 100.f*(m - 1.f) + (4.f*skap - twoK);
            outg[j0 + 1] = __fdividef(1.f, 1.f + __expf(-gm*invt));
            float ent = xv*__logf(xv + EPSF) + x_1*lx1;
            acc += m*( pr*(1.f + 4.f*xv*xt - 2.f*(xv + xt))
                     + (1.f - 2.f*xv)*(Ksum - 2.f*skap) - t*ent );
        }
        __syncthreads();
    }

    // ---- block reduction of acc; emit per-row partial ----
    float ar = wred(acc);
    if ((tid & 31) == 0) redC[tid >> 5] = ar;
    __syncthreads();
    if (tid == 0) {
        float tot = 0.f;
#pragma unroll
        for (int w = 0; w < 16; w++) tot += redC[w];
        g_part[i] = tot + elbrow;
        __threadfence();
        unsigned int old = atomicInc(&g_ctr, NN - 1);   // wraps to 0 after NN incs
        s_last = (old == NN - 1);
    }
    __syncthreads();

    // ---- last block: deterministic final sum in double ----
    if (s_last) {
        double dv = (double)g_part[tid] + (double)g_part[tid + 512];
        double dr = wredd(dv);
        if ((tid & 31) == 0) redD[tid >> 5] = dr;
        __syncthreads();
        if (tid == 0) {
            double tt = 0.0;
#pragma unroll
            for (int w = 0; w < 16; w++) tt += redD[w];
            out[0] = (float)tt;
        }
    }
}

// ---------------------------------------------------------------------------
extern "C" void kernel_launch(void* const* d_in, const int* in_sizes, int n_in,
                              void* d_out, int out_size) {
    const float* X    = (const float*)d_in[0];
    const float* T    = (const float*)d_in[1];
    const float* C    = (const float*)d_in[2];
    const float* D    = (const float*)d_in[3];
    const float* S    = (const float*)d_in[4];
    const float* Mk   = (const float*)d_in[5];
    const float* b0   = (const float*)d_in[6];
    const float* b1   = (const float*)d_in[7];
    const float* b2   = (const float*)d_in[8];
    const float* lam  = (const float*)d_in[9];
    const float* eta  = (const float*)d_in[10];
    const float* nu   = (const float*)d_in[11];
    const float* mu   = (const float*)d_in[12];
    const float* kap  = (const float*)d_in[13];
    const int*   iij  = (const int*)d_in[14];
    const int*   iijF = (const int*)d_in[15];
    const int*   iijT = (const int*)d_in[16];
    const int*   iiT  = (const int*)d_in[17];
    float* out = (float*)d_out;

    k_transpose<<<dim3(32, 32), dim3(32, 8)>>>(X);
    k_main<<<NN, 512>>>(X, C, D, S, Mk, T, b0, b1, b2, lam, eta, nu, mu, kap,
                        iij, iijF, iijT, iiT, out);
}